// round 16
// baseline (speedup 1.0000x reference)
#include <cuda_runtime.h>
#include <cstddef>

// 2-layer LSTM (H=20) + FC head, B=4096, T=512, D=1.
// 128-thread blocks, 16 seqs/block, grid 256 -> 2 independent blocks per SM
// (independent barriers = phase drift). Every warp identical: warp w owns
// units 5w..5w+4 of BOTH layers; half-warp 0 computes (i,f) pair-rows,
// half-warp 1 the (g,o) rows; cell via shfl_xor(16) role exchange (R5-style),
// c duplicated per half. R13 fused pipeline: iter k = layer0 step k +
// layer1 step k-1, ONE __syncthreads per iteration.

using u64 = unsigned long long;

__device__ __forceinline__ u64 fma2(u64 a, u64 b, u64 c) {
    u64 d;
    asm("fma.rn.f32x2 %0, %1, %2, %3;" : "=l"(d) : "l"(a), "l"(b), "l"(c));
    return d;
}
__device__ __forceinline__ u64 pk2(float lo, float hi) {
    u64 r;
    asm("mov.b64 %0, {%1, %2};" : "=l"(r) : "f"(lo), "f"(hi));
    return r;
}
__device__ __forceinline__ void up2(float& lo, float& hi, u64 v) {
    asm("mov.b64 {%0, %1}, %2;" : "=f"(lo), "=f"(hi) : "l"(v));
}
__device__ __forceinline__ float ex2_(float x) {
    float y; asm("ex2.approx.f32 %0, %1;" : "=f"(y) : "f"(x)); return y;
}
__device__ __forceinline__ float rcp_(float x) {
    float y; asm("rcp.approx.f32 %0, %1;" : "=f"(y) : "f"(x)); return y;
}

#define L2E 1.4426950408889634f

__device__ __forceinline__ float tanhx_(float x) {
    return fmaf(2.0f, rcp_(1.0f + ex2_(-2.0f * L2E * x)), -1.0f);
}

// pair p in [0,40): p<20 -> rows (p, 20+p) = (i,f) of unit p
//                   p>=20 -> rows (40+j, 60+j) = (g,o) of unit j=p-20
__global__ void __launch_bounds__(128, 2) lstm2_fc_kernel(
    const float* __restrict__ x,     // [B, T]
    const float* __restrict__ Wih0,  // [80, 1]
    const float* __restrict__ Whh0,  // [80, 20]
    const float* __restrict__ bih0,  // [80]
    const float* __restrict__ bhh0,  // [80]
    const float* __restrict__ Wih1,  // [80, 20]
    const float* __restrict__ Whh1,  // [80, 20]
    const float* __restrict__ bih1,  // [80]
    const float* __restrict__ bhh1,  // [80]
    const float* __restrict__ fcW,   // [1, 20]
    const float* __restrict__ fcb,   // [1]
    float* __restrict__ out,         // [B, 1]
    int Btot, int Tlen)
{
    __shared__ __align__(16) u64 w0s[40 * 20];       // pair-packed Whh0
    __shared__ __align__(16) u64 w1s[40 * 40];       // pair-packed [Wih1|Whh1]
    __shared__ __align__(16) float h0d[2][20 * 16];  // double-buffered h0
    __shared__ __align__(16) float h1d[2][20 * 16];  // double-buffered h1
    __shared__ __align__(16) float xsd[2][16 * 16];  // double-buffered x tiles

    const int tid = threadIdx.x;

    // ---- pack weights (pair layout), 128 threads ----
    for (int idx = tid; idx < 800; idx += 128) {
        int p = idx / 20, m = idx % 20;
        int j = (p < 20) ? p : (p - 20);
        int rlo = (p < 20) ? j : (40 + j);
        int rhi = rlo + 20;
        w0s[p * 20 + m] = pk2(Whh0[rlo * 20 + m], Whh0[rhi * 20 + m]);
    }
    for (int idx = tid; idx < 1600; idx += 128) {
        int p = idx / 40, mm = idx % 40;
        int j = (p < 20) ? p : (p - 20);
        int rlo = (p < 20) ? j : (40 + j);
        int rhi = rlo + 20;
        const float* mat = (mm < 20) ? Wih1 : Whh1;
        int m = (mm < 20) ? mm : (mm - 20);
        w1s[p * 40 + mm] = pk2(mat[rlo * 20 + m], mat[rhi * 20 + m]);
    }
    for (int idx = tid; idx < 2 * 320; idx += 128) {
        h0d[idx / 320][idx % 320] = 0.f;
        h1d[idx / 320][idx % 320] = 0.f;
    }

    const int w    = tid >> 5;      // warp 0..3: owns units 5w..5w+4, both layers
    const int lane = tid & 31;
    const int hf   = lane >> 4;     // half: 0 = (i,f) rows, 1 = (g,o) rows
    const int s    = lane & 15;     // sequence within block
    const bool isGO = (hf == 1);
    const int pb   = hf * 20 + 5 * w;   // first owned pair-row
    const int u0   = 5 * w;             // first owned unit
    const int b0g  = blockIdx.x * 16;

    // ---- stage x tile 0 ----
    {
        int sq = tid & 15, tt2 = tid >> 4;   // tt2 0..7
        int bb = b0g + sq;
        const float* xrow = x + (size_t)((bb < Btot) ? bb : (Btot - 1)) * Tlen;
        #pragma unroll
        for (int ii = 0; ii < 2; ++ii) {
            int tt = tt2 * 2 + ii;
            xsd[0][tt * 16 + sq] = (tt < Tlen && bb < Btot) ? __ldg(&xrow[tt]) : 0.f;
        }
    }

    // per-lane pair constants (uniform within each half)
    u64 cst0[5], cst1[5], wx0[5];
    #pragma unroll
    for (int jl = 0; jl < 5; ++jl) {
        int pp = pb + jl;
        int j = (pp < 20) ? pp : (pp - 20);
        int rlo = (pp < 20) ? j : (40 + j);
        int rhi = rlo + 20;
        cst0[jl] = pk2(__ldg(&bih0[rlo]) + __ldg(&bhh0[rlo]),
                       __ldg(&bih0[rhi]) + __ldg(&bhh0[rhi]));
        cst1[jl] = pk2(__ldg(&bih1[rlo]) + __ldg(&bhh1[rlo]),
                       __ldg(&bih1[rhi]) + __ldg(&bhh1[rhi]));
        wx0[jl]  = pk2(__ldg(&Wih0[rlo]), __ldg(&Wih0[rhi]));
    }

    // branchless role activation constants:
    // lo-gate: half0 -> sigmoid(i), half1 -> tanh(g); hi-gate: sigmoid (f / o)
    const float kk0 = isGO ? (-2.0f * L2E) : (-L2E);
    const float kb2 = isGO ? 2.0f : 1.0f;
    const float kb3 = isGO ? -1.0f : 0.0f;

    __syncthreads();

    float c0[5] = {0.f, 0.f, 0.f, 0.f, 0.f};   // duplicated on both halves
    float c1[5] = {0.f, 0.f, 0.f, 0.f, 0.f};

    const unsigned FULL = 0xffffffffu;

    #pragma unroll 1
    for (int k = 0; k <= Tlen; ++k) {
        // ================= layer0, step k =================
        if (k < Tlen) {
            float xv = xsd[(k >> 4) & 1][(k & 15) * 16 + s];
            u64 x2 = pk2(xv, xv);
            u64 acc[5];
            #pragma unroll
            for (int jl = 0; jl < 5; ++jl) acc[jl] = fma2(wx0[jl], x2, cst0[jl]);
            const float* hp = &h0d[(k + 1) & 1][0];       // h0(k-1)
            #pragma unroll
            for (int m2 = 0; m2 < 10; ++m2) {
                float a0 = hp[(2 * m2) * 16 + s];
                float b0 = hp[(2 * m2 + 1) * 16 + s];
                u64 h2a = pk2(a0, a0), h2b = pk2(b0, b0);
                #pragma unroll
                for (int jl = 0; jl < 5; ++jl) {
                    ulonglong2 wv = *reinterpret_cast<const ulonglong2*>(&w0s[(pb + jl) * 20 + 2 * m2]);
                    acc[jl] = fma2(wv.x, h2a, acc[jl]);
                    acc[jl] = fma2(wv.y, h2b, acc[jl]);
                }
            }
            float* hw = &h0d[k & 1][0];                   // h0(k)
            #pragma unroll
            for (int jl = 0; jl < 5; ++jl) {
                float lo, hi;
                up2(lo, hi, acc[jl]);
                float alo = fmaf(kb2, rcp_(1.0f + ex2_(kk0 * lo)), kb3);  // i | g
                float ahi = rcp_(1.0f + ex2_(-L2E * hi));                  // f | o
                float xlo = __shfl_xor_sync(FULL, alo, 16);
                float xhi = __shfl_xor_sync(FULL, ahi, 16);
                float gi = isGO ? xlo : alo, gg = isGO ? alo : xlo;
                float gf = isGO ? xhi : ahi, go = isGO ? ahi : xhi;
                float cn = fmaf(gf, c0[jl], gi * gg);
                c0[jl] = cn;
                float hv = go * tanhx_(cn);
                if (!isGO) hw[(u0 + jl) * 16 + s] = hv;
            }
        }

        // ================= layer1, step k-1 =================
        if (k >= 1) {
            u64 acc[5];
            #pragma unroll
            for (int jl = 0; jl < 5; ++jl) acc[jl] = cst1[jl];
            const float* hp0 = &h0d[(k + 1) & 1][0];      // h0(k-1)
            const float* hp1 = &h1d[k & 1][0];            // h1(k-2)
            #pragma unroll
            for (int m2 = 0; m2 < 10; ++m2) {
                float a0 = hp0[(2 * m2) * 16 + s];
                float b0 = hp0[(2 * m2 + 1) * 16 + s];
                float a1 = hp1[(2 * m2) * 16 + s];
                float b1 = hp1[(2 * m2 + 1) * 16 + s];
                u64 h2a0 = pk2(a0, a0), h2b0 = pk2(b0, b0);
                u64 h2a1 = pk2(a1, a1), h2b1 = pk2(b1, b1);
                #pragma unroll
                for (int jl = 0; jl < 5; ++jl) {
                    ulonglong2 wu = *reinterpret_cast<const ulonglong2*>(&w1s[(pb + jl) * 40 + 2 * m2]);
                    ulonglong2 wv = *reinterpret_cast<const ulonglong2*>(&w1s[(pb + jl) * 40 + 20 + 2 * m2]);
                    acc[jl] = fma2(wu.x, h2a0, acc[jl]);
                    acc[jl] = fma2(wu.y, h2b0, acc[jl]);
                    acc[jl] = fma2(wv.x, h2a1, acc[jl]);
                    acc[jl] = fma2(wv.y, h2b1, acc[jl]);
                }
            }
            float* hw = &h1d[(k + 1) & 1][0];             // h1(k-1)
            #pragma unroll
            for (int jl = 0; jl < 5; ++jl) {
                float lo, hi;
                up2(lo, hi, acc[jl]);
                float alo = fmaf(kb2, rcp_(1.0f + ex2_(kk0 * lo)), kb3);
                float ahi = rcp_(1.0f + ex2_(-L2E * hi));
                float xlo = __shfl_xor_sync(FULL, alo, 16);
                float xhi = __shfl_xor_sync(FULL, ahi, 16);
                float gi = isGO ? xlo : alo, gg = isGO ? alo : xlo;
                float gf = isGO ? xhi : ahi, go = isGO ? ahi : xhi;
                float cn = fmaf(gf, c1[jl], gi * gg);
                c1[jl] = cn;
                float hv = go * tanhx_(cn);
                if (!isGO) hw[(u0 + jl) * 16 + s] = hv;
            }
        }

        // stage next x tile (written to OPPOSITE parity; used after barrier)
        if ((k & 15) == 15 && (k + 1) < Tlen) {
            float* xd = xsd[((k + 1) >> 4) & 1];
            int sq = tid & 15, tt2 = tid >> 4;
            int bb = b0g + sq;
            const float* xrow = x + (size_t)((bb < Btot) ? bb : (Btot - 1)) * Tlen;
            #pragma unroll
            for (int ii = 0; ii < 2; ++ii) {
                int tt = tt2 * 2 + ii;
                int tg = k + 1 + tt;
                xd[tt * 16 + sq] = (tg < Tlen && bb < Btot) ? __ldg(&xrow[tg]) : 0.f;
            }
        }
        __syncthreads();
    }

    // ---- FC head: h1(T-1) lives in h1d[(Tlen)&1] slot written at k=Tlen ----
    if (tid < 16) {
        const float* hfm = &h1d[(Tlen + 1) & 1][0];   // written at k=Tlen -> (k+1)&1
        float acc = __ldg(&fcb[0]);
        #pragma unroll
        for (int j = 0; j < 20; ++j)
            acc = fmaf(__ldg(&fcW[j]), hfm[j * 16 + tid], acc);
        int bo = b0g + tid;
        if (bo < Btot) out[bo] = acc;
    }
}

extern "C" void kernel_launch(void* const* d_in, const int* in_sizes, int n_in,
                              void* d_out, int out_size)
{
    const float* x    = (const float*)d_in[0];
    const float* Wih0 = (const float*)d_in[1];
    const float* Whh0 = (const float*)d_in[2];
    const float* bih0 = (const float*)d_in[3];
    const float* bhh0 = (const float*)d_in[4];
    const float* Wih1 = (const float*)d_in[5];
    const float* Whh1 = (const float*)d_in[6];
    const float* bih1 = (const float*)d_in[7];
    const float* bhh1 = (const float*)d_in[8];
    const float* fcW  = (const float*)d_in[9];
    const float* fcb  = (const float*)d_in[10];

    const int B = out_size;              // out is [B, 1] fp32
    const int T = in_sizes[0] / B;       // x is [B, T, 1]
    const int blocks = (B + 15) / 16;    // 16 seqs per 128-thread block

    lstm2_fc_kernel<<<blocks, 128>>>(x, Wih0, Whh0, bih0, bhh0,
                                     Wih1, Whh1, bih1, bhh1,
                                     fcW, fcb, (float*)d_out, B, T);
}

// round 17
// speedup vs baseline: 1.0018x; 1.0018x over previous
#include <cuda_runtime.h>
#include <cstddef>

// 2-layer LSTM (H=20) + FC head, B=4096, T=512, D=1.
// 128-thread blocks, 32 seqs/block (lane = sequence), grid 128.
// FUSED-PER-WARP: each of the 4 identical warps owns units 5w..5w+4 of BOTH
// layers. Iteration k computes layer0 step k AND layer1 step k-1 (independent
// given h0(k-1)) -> 20 independent FMA chains + adjacent independent MUFU cell
// work inside ONE warp. h0(k-1) loads shared by both matvecs. 1 barrier/step.

using u64 = unsigned long long;

__device__ __forceinline__ u64 fma2(u64 a, u64 b, u64 c) {
    u64 d;
    asm("fma.rn.f32x2 %0, %1, %2, %3;" : "=l"(d) : "l"(a), "l"(b), "l"(c));
    return d;
}
__device__ __forceinline__ u64 pk2(float lo, float hi) {
    u64 r;
    asm("mov.b64 %0, {%1, %2};" : "=l"(r) : "f"(lo), "f"(hi));
    return r;
}
__device__ __forceinline__ void up2(float& lo, float& hi, u64 v) {
    asm("mov.b64 {%0, %1}, %2;" : "=f"(lo), "=f"(hi) : "l"(v));
}
__device__ __forceinline__ float ex2_(float x) {
    float y; asm("ex2.approx.f32 %0, %1;" : "=f"(y) : "f"(x)); return y;
}
__device__ __forceinline__ float rcp_(float x) {
    float y; asm("rcp.approx.f32 %0, %1;" : "=f"(y) : "f"(x)); return y;
}

#define L2E 1.4426950408889634f

__device__ __forceinline__ float sigm_(float x) {
    return rcp_(1.0f + ex2_(-L2E * x));
}
__device__ __forceinline__ float tanhx_(float x) {
    return fmaf(2.0f, rcp_(1.0f + ex2_(-2.0f * L2E * x)), -1.0f);
}

// pair p in [0,40): p<20 -> rows (p, 20+p) = (i,f) of unit p
//                   p>=20 -> rows (40+j, 60+j) = (g,o) of unit j=p-20
__global__ void __launch_bounds__(128, 1) lstm2_fc_kernel(
    const float* __restrict__ x,     // [B, T]
    const float* __restrict__ Wih0,  // [80, 1]
    const float* __restrict__ Whh0,  // [80, 20]
    const float* __restrict__ bih0,  // [80]
    const float* __restrict__ bhh0,  // [80]
    const float* __restrict__ Wih1,  // [80, 20]
    const float* __restrict__ Whh1,  // [80, 20]
    const float* __restrict__ bih1,  // [80]
    const float* __restrict__ bhh1,  // [80]
    const float* __restrict__ fcW,   // [1, 20]
    const float* __restrict__ fcb,   // [1]
    float* __restrict__ out,         // [B, 1]
    int Btot, int Tlen)
{
    __shared__ __align__(16) u64 w0s[40 * 20];       // pair-packed Whh0
    __shared__ __align__(16) u64 w1s[40 * 40];       // pair-packed [Wih1|Whh1]
    __shared__ __align__(16) float h0d[2][20 * 32];  // double-buffered h0
    __shared__ __align__(16) float h1d[2][20 * 32];  // double-buffered h1
    __shared__ __align__(16) float xsd[2][16 * 32];  // double-buffered x tiles

    const int tid = threadIdx.x;

    // ---- pack weights (pair layout), 128 threads ----
    for (int idx = tid; idx < 800; idx += 128) {
        int p = idx / 20, m = idx % 20;
        int j = (p < 20) ? p : (p - 20);
        int rlo = (p < 20) ? j : (40 + j);
        int rhi = rlo + 20;
        w0s[p * 20 + m] = pk2(Whh0[rlo * 20 + m], Whh0[rhi * 20 + m]);
    }
    for (int idx = tid; idx < 1600; idx += 128) {
        int p = idx / 40, mm = idx % 40;
        int j = (p < 20) ? p : (p - 20);
        int rlo = (p < 20) ? j : (40 + j);
        int rhi = rlo + 20;
        const float* mat = (mm < 20) ? Wih1 : Whh1;
        int m = (mm < 20) ? mm : (mm - 20);
        w1s[p * 40 + mm] = pk2(mat[rlo * 20 + m], mat[rhi * 20 + m]);
    }
    for (int idx = tid; idx < 2 * 640; idx += 128) {
        h0d[idx / 640][idx % 640] = 0.f;
        h1d[idx / 640][idx % 640] = 0.f;
    }

    const int w = tid >> 5;         // warp 0..3: owns units 5w..5w+4, BOTH layers
    const int s = tid & 31;         // lane = sequence
    const int u0 = 5 * w;           // first owned unit
    const int b0g = blockIdx.x * 32;

    // ---- stage x tile 0 ----
    {
        int sq = tid & 31, tt2 = tid >> 5;   // tt2 0..3
        int bb = b0g + sq;
        const float* xrow = x + (size_t)((bb < Btot) ? bb : (Btot - 1)) * Tlen;
        #pragma unroll
        for (int ii = 0; ii < 4; ++ii) {
            int tt = tt2 * 4 + ii;
            xsd[0][tt * 32 + sq] = (tt < Tlen && bb < Btot) ? __ldg(&xrow[tt]) : 0.f;
        }
    }

    // per-warp pair constants: i<5 -> IF pair of unit u0+i ; i>=5 -> GO pair
    u64 cst0[10], cst1[10], wx0[10];
    #pragma unroll
    for (int i = 0; i < 10; ++i) {
        int pp = (i < 5) ? (u0 + i) : (15 + u0 + i);
        int j = (pp < 20) ? pp : (pp - 20);
        int rlo = (pp < 20) ? j : (40 + j);
        int rhi = rlo + 20;
        cst0[i] = pk2(__ldg(&bih0[rlo]) + __ldg(&bhh0[rlo]),
                      __ldg(&bih0[rhi]) + __ldg(&bhh0[rhi]));
        cst1[i] = pk2(__ldg(&bih1[rlo]) + __ldg(&bhh1[rlo]),
                      __ldg(&bih1[rhi]) + __ldg(&bhh1[rhi]));
        wx0[i]  = pk2(__ldg(&Wih0[rlo]), __ldg(&Wih0[rhi]));
    }

    __syncthreads();

    float c0[5] = {0.f, 0.f, 0.f, 0.f, 0.f};
    float c1[5] = {0.f, 0.f, 0.f, 0.f, 0.f};

    #pragma unroll 1
    for (int k = 0; k <= Tlen; ++k) {
        const bool doL0 = (k < Tlen);
        const bool doL1 = (k >= 1);

        u64 acc0[10], acc1[10];
        {
            float xv = doL0 ? xsd[(k >> 4) & 1][(k & 15) * 32 + s] : 0.f;
            u64 x2 = pk2(xv, xv);
            #pragma unroll
            for (int i = 0; i < 10; ++i) {
                acc0[i] = fma2(wx0[i], x2, cst0[i]);
                acc1[i] = cst1[i];
            }
        }

        // ---- pass 1: h0(k-1) feeds BOTH matvecs (shared loads) ----
        const float* hp0 = &h0d[(k + 1) & 1][0];          // h0(k-1)
        #pragma unroll
        for (int m2 = 0; m2 < 10; ++m2) {
            float a0 = hp0[(2 * m2) * 32 + s];
            float b0 = hp0[(2 * m2 + 1) * 32 + s];
            u64 h2a = pk2(a0, a0), h2b = pk2(b0, b0);
            #pragma unroll
            for (int i = 0; i < 10; ++i) {
                int pp = (i < 5) ? (u0 + i) : (15 + u0 + i);
                ulonglong2 w0v = *reinterpret_cast<const ulonglong2*>(&w0s[pp * 20 + 2 * m2]);
                ulonglong2 w1u = *reinterpret_cast<const ulonglong2*>(&w1s[pp * 40 + 2 * m2]);
                acc0[i] = fma2(w0v.x, h2a, acc0[i]);
                acc0[i] = fma2(w0v.y, h2b, acc0[i]);
                acc1[i] = fma2(w1u.x, h2a, acc1[i]);
                acc1[i] = fma2(w1u.y, h2b, acc1[i]);
            }
        }

        // ---- pass 2: h1(k-2) feeds layer1 recurrence ----
        const float* hp1 = &h1d[k & 1][0];                // h1(k-2)
        #pragma unroll
        for (int m2 = 0; m2 < 10; ++m2) {
            float a1 = hp1[(2 * m2) * 32 + s];
            float b1 = hp1[(2 * m2 + 1) * 32 + s];
            u64 h2a = pk2(a1, a1), h2b = pk2(b1, b1);
            #pragma unroll
            for (int i = 0; i < 10; ++i) {
                int pp = (i < 5) ? (u0 + i) : (15 + u0 + i);
                ulonglong2 w1v = *reinterpret_cast<const ulonglong2*>(&w1s[pp * 40 + 20 + 2 * m2]);
                acc1[i] = fma2(w1v.x, h2a, acc1[i]);
                acc1[i] = fma2(w1v.y, h2b, acc1[i]);
            }
        }

        // ---- cells: layer0 step k and layer1 step k-1 (independent) ----
        if (doL0) {
            float* hw = &h0d[k & 1][0];                   // h0(k)
            #pragma unroll
            for (int jl = 0; jl < 5; ++jl) {
                float gi, gf, gg, go;
                up2(gi, gf, acc0[jl]);
                up2(gg, go, acc0[5 + jl]);
                float ai = sigm_(gi), af = sigm_(gf);
                float ag = tanhx_(gg), ao = sigm_(go);
                float cn = fmaf(af, c0[jl], ai * ag);
                c0[jl] = cn;
                hw[(u0 + jl) * 32 + s] = ao * tanhx_(cn);
            }
        }
        if (doL1) {
            float* hw = &h1d[(k + 1) & 1][0];             // h1(k-1)
            #pragma unroll
            for (int jl = 0; jl < 5; ++jl) {
                float gi, gf, gg, go;
                up2(gi, gf, acc1[jl]);
                up2(gg, go, acc1[5 + jl]);
                float ai = sigm_(gi), af = sigm_(gf);
                float ag = tanhx_(gg), ao = sigm_(go);
                float cn = fmaf(af, c1[jl], ai * ag);
                c1[jl] = cn;
                hw[(u0 + jl) * 32 + s] = ao * tanhx_(cn);
            }
        }

        // stage next x tile (opposite parity; consumed after barrier)
        if ((k & 15) == 15 && (k + 1) < Tlen) {
            float* xd = xsd[((k + 1) >> 4) & 1];
            int sq = tid & 31, tt2 = tid >> 5;
            int bb = b0g + sq;
            const float* xrow = x + (size_t)((bb < Btot) ? bb : (Btot - 1)) * Tlen;
            #pragma unroll
            for (int ii = 0; ii < 4; ++ii) {
                int tt = tt2 * 4 + ii;
                int tg = k + 1 + tt;
                xd[tt * 32 + sq] = (tg < Tlen && bb < Btot) ? __ldg(&xrow[tg]) : 0.f;
            }
        }
        __syncthreads();
    }

    // ---- FC head: h1(T-1) written at k=Tlen into h1d[(Tlen+1)&1] ----
    if (tid < 32) {
        const float* hf = &h1d[(Tlen + 1) & 1][0];
        float acc = __ldg(&fcb[0]);
        #pragma unroll
        for (int j = 0; j < 20; ++j)
            acc = fmaf(__ldg(&fcW[j]), hf[j * 32 + tid], acc);
        int bo = b0g + tid;
        if (bo < Btot) out[bo] = acc;
    }
}

extern "C" void kernel_launch(void* const* d_in, const int* in_sizes, int n_in,
                              void* d_out, int out_size)
{
    const float* x    = (const float*)d_in[0];
    const float* Wih0 = (const float*)d_in[1];
    const float* Whh0 = (const float*)d_in[2];
    const float* bih0 = (const float*)d_in[3];
    const float* bhh0 = (const float*)d_in[4];
    const float* Wih1 = (const float*)d_in[5];
    const float* Whh1 = (const float*)d_in[6];
    const float* bih1 = (const float*)d_in[7];
    const float* bhh1 = (const float*)d_in[8];
    const float* fcW  = (const float*)d_in[9];
    const float* fcb  = (const float*)d_in[10];

    const int B = out_size;              // out is [B, 1] fp32
    const int T = in_sizes[0] / B;       // x is [B, T, 1]
    const int blocks = (B + 31) / 32;    // 32 seqs per 128-thread block

    lstm2_fc_kernel<<<blocks, 128>>>(x, Wih0, Whh0, bih0, bhh0,
                                     Wih1, Whh1, bih1, bhh1,
                                     fcW, fcb, (float*)d_out, B, T);
}